// round 12
// baseline (speedup 1.0000x reference)
#include <cuda_runtime.h>
#include <cstdint>
#include <cstddef>

// ---------------------------------------------------------------------------
// GRU-D imputer, fp32, f32x2 FMA, 512-thread CTAs (16 warps/SM),
// SINGLE-barrier recurrent loop (double-buffered hv, direct STG epilogue).
//   Kernel 1 (recurrent): 128 CTAs x 512 thr, 8 batch rows/CTA, T=1024.
//     Thread tile: 6 outputs x 1 row. One __syncthreads per step.
//   Kernel 2 (heads): 1024 CTAs x 512 thr, 16-row tiles, 6x1 thread tiles,
//     gmem h-tile register prefetch.
// ---------------------------------------------------------------------------

namespace {
constexpr int B = 1024, T = 1024, H = 128, C = 6;
constexpr int G3 = 3 * H;        // 384
constexpr int XD = 2 * C + 1;    // 13
constexpr int HP = 140;          // pitch for Ws / hv rows (128 h + 12 gru_in)
constexpr int NB = 8;            // batch rows per CTA (kernel 1)
constexpr int WP2 = 132;         // pitch kernel 2
}

// 512 MB scratch for the h history (module-static; no runtime allocation).
__device__ float g_h[(size_t)B * T * H];

__device__ __forceinline__ void fma2(unsigned long long& d,
                                     unsigned long long a,
                                     unsigned long long b) {
    asm("fma.rn.f32x2 %0, %1, %2, %0;" : "+l"(d) : "l"(a), "l"(b));
}
__device__ __forceinline__ float hsum2(unsigned long long v) {
    float lo, hi;
    asm("mov.b64 {%0, %1}, %2;" : "=f"(lo), "=f"(hi) : "l"(v));
    return lo + hi;
}
__device__ __forceinline__ float sigf(float x) {
    return 1.f / (1.f + __expf(-x));
}

// ---------------------------------------------------------------------------
// Kernel 1: recurrent scan
//   tid = jg*8 + r ; jg in [0,64) output group, r in [0,8) batch row.
//   Thread owns outputs j = jg + 64*i (i=0..5) for its single row:
//     i=0,1 -> r-gate of units {jg, jg+64}; i=2,3 -> z; i=4,5 -> n.
//   Per step: write hv[t&1] -> BAR -> GEMM(read hv[t&1]) -> STG h to g_h.
//   WAR on hv[t&1] (rewritten at t+2) is fenced by BAR at t+1: race-free
//   with exactly one barrier per step.
// ---------------------------------------------------------------------------
__global__ void __launch_bounds__(512, 1) grud_recurrent(
    const float* __restrict__ x,
    const float* __restrict__ x_mean,
    const float* __restrict__ dxw_g, const float* __restrict__ dxb_g,
    const float* __restrict__ dhw_g, const float* __restrict__ dhb_g,
    const float* __restrict__ w_ih, const float* __restrict__ w_hh,
    const float* __restrict__ b_ih, const float* __restrict__ b_hh)
{
    extern __shared__ float sm[];
    float* Ws  = sm;                   // [384][HP]  combined [w_hh | w_ih]
    float* hv0 = Ws + G3 * HP;         // [8][HP]    buffer 0
    float* hv1 = hv0 + NB * HP;        // [8][HP]    buffer 1

    const int tid  = threadIdx.x;
    const int r    = tid & 7;          // batch row within CTA
    const int jg   = tid >> 3;         // 0..63
    const int b0   = blockIdx.x * NB;

    // Fill combined weight tile: cols 0..127 = w_hh, 128..139 = w_ih.
    for (int idx = tid; idx < G3 * H; idx += 512)
        Ws[(idx >> 7) * HP + (idx & 127)] = w_hh[idx];
    for (int idx = tid; idx < G3 * 12; idx += 512)
        Ws[(idx / 12) * HP + H + (idx % 12)] = w_ih[idx];

    // Per-thread constants.
    float bc[4], bhn[2], bin[2];                 // combined r/z biases, n biases
    #pragma unroll
    for (int i = 0; i < 4; i++) {
        int j = jg + 64 * i;
        bc[i] = b_ih[j] + b_hh[j];
    }
    #pragma unroll
    for (int iu = 0; iu < 2; iu++) {
        int j = 256 + jg + 64 * iu;
        bhn[iu] = b_hh[j]; bin[iu] = b_ih[j];
    }
    float dhw[2], dhb[2];
    #pragma unroll
    for (int iu = 0; iu < 2; iu++) { dhw[iu] = dhw_g[jg + 64 * iu]; dhb[iu] = dhb_g[jg + 64 * iu]; }
    float dxw = 0.f, dxb = 0.f, xm = 0.f;
    if (jg < C) { dxw = dxw_g[jg]; dxb = dxb_g[jg]; xm = x_mean[jg]; }

    float hprev[2] = {0.f, 0.f};       // [iu]
    float running = 0.f, xlast = 0.f;

    // Output base for this thread's 2 direct h stores.
    float* gout = &g_h[((size_t)(b0 + r) * T) * H + jg];

    // Prefetch x(t=0) for this thread's row.
    const size_t xb = ((size_t)(b0 + r) * T) * XD;
    float p_dt, p_xv = 0.f, p_mv = 0.f;
    p_dt = x[xb + 12];
    if (jg < C) { p_xv = x[xb + jg]; p_mv = x[xb + C + jg]; }

    __syncthreads();

    for (int t = 0; t < T; t++) {
        float* hv = (t & 1) ? hv1 : hv0;

        const float dtv = p_dt, xvv = p_xv, mvv = p_mv;

        // Prefetch x(t+1): hides LDG latency behind this step's GEMM.
        if (t + 1 < T) {
            size_t o = xb + (size_t)(t + 1) * XD;
            p_dt = x[o + 12];
            if (jg < C) { p_xv = x[o + jg]; p_mv = x[o + C + jg]; }
        }

        // h_dec = gamma_h * h_prev (2 states in registers).
        float hd[2];
        #pragma unroll
        for (int iu = 0; iu < 2; iu++) {
            float g = __expf(-fmaxf(fmaf(dtv, dhw[iu], dhb[iu]), 0.f));
            float v = g * hprev[iu];
            hd[iu] = v;
            hv[r * HP + jg + 64 * iu] = v;
        }
        // Input scans + x_hat (threads jg<6 own feature c=jg of row r).
        if (jg < C) {
            float xv = xvv, m = mvv;
            bool obs = (m > 0.5f);
            running = obs ? 0.f : (running + dtv);
            float gx = __expf(-fmaxf(fmaf(running, dxw, dxb), 0.f));
            xlast = obs ? xv : xlast;
            float xh = m * xv + (1.f - m) * (gx * xlast + (1.f - gx) * xm);
            hv[r * HP + H + jg]     = xh;   // gru_in[0:6]  = x_hat
            hv[r * HP + H + C + jg] = m;    // gru_in[6:12] = m
        }
        __syncthreads();   // the ONLY barrier per step

        // GEMM: 6 outputs x 1 row; K=140 in 16B chunks (fully unrolled —
        // ptxas pipelines the LDS across chunks).
        // Chunks 0..31: h-part. Chunks 32..34 (gru_in): i<4 fold into acch
        // (r/z need only the sum); i=4,5 go to acci (n = tanh(gi_n + r*gh_n)).
        unsigned long long acch[6], acci[2];
        #pragma unroll
        for (int i = 0; i < 6; i++) acch[i] = 0ull;
        acci[0] = 0ull; acci[1] = 0ull;

        const float* hrow = &hv[r * HP];
        const float* wb   = &Ws[jg * HP];
        #pragma unroll
        for (int kb = 0; kb < 32; kb++) {
            ulonglong2 hp = *(const ulonglong2*)&hrow[4 * kb];
            #pragma unroll
            for (int i = 0; i < 6; i++) {
                ulonglong2 wp = *(const ulonglong2*)&wb[(i * 64) * HP + 4 * kb];
                fma2(acch[i], hp.x, wp.x);
                fma2(acch[i], hp.y, wp.y);
            }
        }
        #pragma unroll
        for (int kb = 32; kb < 35; kb++) {
            ulonglong2 hp = *(const ulonglong2*)&hrow[4 * kb];
            #pragma unroll
            for (int i = 0; i < 4; i++) {           // r,z: fold gi into acch
                ulonglong2 wp = *(const ulonglong2*)&wb[(i * 64) * HP + 4 * kb];
                fma2(acch[i], hp.x, wp.x);
                fma2(acch[i], hp.y, wp.y);
            }
            #pragma unroll
            for (int iu = 0; iu < 2; iu++) {        // n: gi kept separate
                ulonglong2 wp = *(const ulonglong2*)&wb[((4 + iu) * 64) * HP + 4 * kb];
                fma2(acci[iu], hp.x, wp.x);
                fma2(acci[iu], hp.y, wp.y);
            }
        }

        // Gates + state update; store h directly to g_h (2 STG.32).
        float* gt = gout + (size_t)t * H;
        #pragma unroll
        for (int iu = 0; iu < 2; iu++) {
            float rg  = sigf(hsum2(acch[iu])     + bc[iu]);
            float z   = sigf(hsum2(acch[2 + iu]) + bc[2 + iu]);
            float ghn = hsum2(acch[4 + iu]) + bhn[iu];
            float gin = hsum2(acci[iu])     + bin[iu];
            float n   = tanhf(fmaf(rg, ghn, gin));
            float hn  = fmaf(z, hd[iu] - n, n);   // (1-z)*n + z*h_dec
            hprev[iu] = hn;
            gt[64 * iu] = hn;
        }
    }
}

// ---------------------------------------------------------------------------
// Kernel 2: output heads over 1M rows; 16-row tiles, 6x1 thread tiles.
//   Stage 1: tid = jg*16 + rp ; jg in [0,32), rp in [0,16).
//     Outputs j = jg + 32*i: i<4 -> w1 rows (128); i=4,5 -> wu1 rows (64).
//   Stage 2: cg = tid&15 (channel), rr2 = tid>>4 (row, guard <16).
// ---------------------------------------------------------------------------
__global__ void __launch_bounds__(512, 1) grud_heads(
    const float* __restrict__ w1,  const float* __restrict__ b1,
    const float* __restrict__ w2,  const float* __restrict__ b2,
    const float* __restrict__ wu1, const float* __restrict__ bu1,
    const float* __restrict__ wu2, const float* __restrict__ bu2,
    float* __restrict__ out_pred, float* __restrict__ out_unc)
{
    extern __shared__ float sm[];
    float* w1s  = sm;                     // [128][WP2]
    float* wu1s = w1s  + H * WP2;         // [64][WP2]
    float* w2s  = wu1s + 64 * WP2;        // [6][WP2]
    float* wu2s = w2s  + C * WP2;         // [6][68]
    float* hts  = wu2s + C * 68;          // [16][WP2]
    float* o1s  = hts  + 16 * WP2;        // [16][WP2]
    float* u1s  = o1s  + 16 * WP2;        // [16][68]

    const int tid = threadIdx.x;
    const int rp  = tid & 15;             // row within tile
    const int jg  = tid >> 4;             // 0..31
    const int cg  = tid & 15;             // stage-2 channel group
    const int rr2 = tid >> 4;             // stage-2 row (guard < 16)

    for (int idx = tid; idx < H * H;  idx += 512) w1s [(idx >> 7) * WP2 + (idx & 127)] = w1[idx];
    for (int idx = tid; idx < 64 * H; idx += 512) wu1s[(idx >> 7) * WP2 + (idx & 127)] = wu1[idx];
    for (int idx = tid; idx < C * H;  idx += 512) w2s [(idx >> 7) * WP2 + (idx & 127)] = w2[idx];
    for (int idx = tid; idx < C * 64; idx += 512) wu2s[(idx >> 6) * 68  + (idx & 63)]  = wu2[idx];

    float bias1[6];
    #pragma unroll
    for (int i = 0; i < 4; i++) bias1[i] = b1[jg + 32 * i];
    bias1[4] = bu1[jg]; bias1[5] = bu1[jg + 32];
    float bias2 = 0.f;
    if (cg < C) bias2 = b2[cg];
    else if (cg >= 8 && cg < 8 + C) bias2 = bu2[cg - 8];
    __syncthreads();

    const int tiles_per_cta = (B * T / 16) / gridDim.x;
    const int tbase = blockIdx.x * tiles_per_cta;

    // h-tile register prefetch: 512 float4 = exactly one per thread.
    const int rw = tid >> 5, k4 = tid & 31;
    float4 pre = *(const float4*)&g_h[((size_t)tbase * 16 + rw) * H + 4 * k4];

    for (int g = 0; g < tiles_per_cta; g++) {
        const size_t row0 = (size_t)(tbase + g) * 16;
        *(float4*)&hts[rw * WP2 + 4 * k4] = pre;
        __syncthreads();

        // Issue next tile's gmem load now; consumed next iteration.
        if (g + 1 < tiles_per_cta)
            pre = *(const float4*)&g_h[(row0 + 16 + rw) * H + 4 * k4];

        unsigned long long a[6];
        #pragma unroll
        for (int i = 0; i < 6; i++) a[i] = 0ull;
        const float* h0 = &hts[rp * WP2];
        #pragma unroll
        for (int kb = 0; kb < 32; kb++) {
            ulonglong2 hp = *(const ulonglong2*)&h0[4 * kb];
            #pragma unroll
            for (int i = 0; i < 4; i++) {
                ulonglong2 wp = *(const ulonglong2*)&w1s[(jg + 32 * i) * WP2 + 4 * kb];
                fma2(a[i], hp.x, wp.x); fma2(a[i], hp.y, wp.y);
            }
            #pragma unroll
            for (int i = 4; i < 6; i++) {
                ulonglong2 wp = *(const ulonglong2*)&wu1s[(jg + 32 * (i - 4)) * WP2 + 4 * kb];
                fma2(a[i], hp.x, wp.x); fma2(a[i], hp.y, wp.y);
            }
        }
        #pragma unroll
        for (int i = 0; i < 4; i++)
            o1s[rp * WP2 + jg + 32 * i] = fmaxf(hsum2(a[i]) + bias1[i], 0.f);
        u1s[rp * 68 + jg]      = fmaxf(hsum2(a[4]) + bias1[4], 0.f);
        u1s[rp * 68 + jg + 32] = fmaxf(hsum2(a[5]) + bias1[5], 0.f);
        __syncthreads();

        // Stage 2: project to C=6 pred / unc channels.
        if (rr2 < 16) {
            if (cg < C) {
                unsigned long long acc = 0ull;
                const float* o = &o1s[rr2 * WP2];
                const float* w = &w2s[cg * WP2];
                #pragma unroll
                for (int kb = 0; kb < 32; kb++) {
                    ulonglong2 op = *(const ulonglong2*)&o[4 * kb];
                    ulonglong2 wp = *(const ulonglong2*)&w[4 * kb];
                    fma2(acc, op.x, wp.x); fma2(acc, op.y, wp.y);
                }
                out_pred[(row0 + rr2) * C + cg] = hsum2(acc) + bias2;
            } else if (cg >= 8 && cg < 8 + C) {
                unsigned long long acc = 0ull;
                const float* u = &u1s[rr2 * 68];
                const float* w = &wu2s[(cg - 8) * 68];
                #pragma unroll
                for (int kb = 0; kb < 16; kb++) {
                    ulonglong2 up = *(const ulonglong2*)&u[4 * kb];
                    ulonglong2 wp = *(const ulonglong2*)&w[4 * kb];
                    fma2(acc, up.x, wp.x); fma2(acc, up.y, wp.y);
                }
                float s = hsum2(acc) + bias2;
                out_unc[(row0 + rr2) * C + (cg - 8)] = (s > 20.f) ? s : log1pf(__expf(s));
            }
        }
        __syncthreads();
    }
}

// ---------------------------------------------------------------------------
// Launch
// ---------------------------------------------------------------------------
extern "C" void kernel_launch(void* const* d_in, const int* in_sizes, int n_in,
                              void* d_out, int out_size) {
    const float* x      = (const float*)d_in[0];
    const float* x_mean = (const float*)d_in[1];
    const float* dxw    = (const float*)d_in[2];
    const float* dxb    = (const float*)d_in[3];
    const float* dhw    = (const float*)d_in[4];
    const float* dhb    = (const float*)d_in[5];
    const float* w_ih   = (const float*)d_in[6];
    const float* w_hh   = (const float*)d_in[7];
    const float* b_ih   = (const float*)d_in[8];
    const float* b_hh   = (const float*)d_in[9];
    const float* w1     = (const float*)d_in[10];
    const float* b1     = (const float*)d_in[11];
    const float* w2     = (const float*)d_in[12];
    const float* b2     = (const float*)d_in[13];
    const float* wu1    = (const float*)d_in[14];
    const float* bu1    = (const float*)d_in[15];
    const float* wu2    = (const float*)d_in[16];
    const float* bu2    = (const float*)d_in[17];

    float* pred = (float*)d_out;
    float* unc  = pred + (size_t)B * T * C;

    const int sm1 = (G3 * HP + 2 * NB * HP) * 4;                             // 224,000 B
    const int sm2 = (H * WP2 + 64 * WP2 + C * WP2 + C * 68 +
                     16 * WP2 + 16 * WP2 + 16 * 68) * 4;                     // 127,424 B

    cudaFuncSetAttribute(grud_recurrent, cudaFuncAttributeMaxDynamicSharedMemorySize, sm1);
    cudaFuncSetAttribute(grud_heads,     cudaFuncAttributeMaxDynamicSharedMemorySize, sm2);

    grud_recurrent<<<B / NB, 512, sm1>>>(x, x_mean, dxw, dxb, dhw, dhb,
                                         w_ih, w_hh, b_ih, b_hh);
    grud_heads<<<1024, 512, sm2>>>(w1, b1, w2, b2, wu1, bu1, wu2, bu2, pred, unc);
}

// round 17
// speedup vs baseline: 1.3514x; 1.3514x over previous
#include <cuda_runtime.h>
#include <cstdint>
#include <cstddef>

// ---------------------------------------------------------------------------
// GRU-D imputer, fp32, f32x2 FMA.
//   Kernel 1: 128 CTAs x 256 thr, (6 out x 2 row) tiles  [R3-proven tiling:
//     2240 LDS.128/step vs 3920 for the 6x1 shape — LDS pipe is the limiter],
//     SINGLE barrier/step (double-buffered hv), direct-STG epilogue.
//   Kernel 2: 1024 CTAs x 256 thr, 16-row tiles, 6x2 thread tiles,
//     gmem h-tile register prefetch.
// ---------------------------------------------------------------------------

namespace {
constexpr int B = 1024, T = 1024, H = 128, C = 6;
constexpr int G3 = 3 * H;        // 384
constexpr int XD = 2 * C + 1;    // 13
constexpr int HP = 140;          // pitch for Ws / hv rows (128 h + 12 gru_in)
constexpr int NB = 8;            // batch rows per CTA (kernel 1)
constexpr int WP2 = 132;         // pitch kernel 2
}

// 512 MB scratch for the h history (module-static; no runtime allocation).
__device__ float g_h[(size_t)B * T * H];

__device__ __forceinline__ void fma2(unsigned long long& d,
                                     unsigned long long a,
                                     unsigned long long b) {
    asm("fma.rn.f32x2 %0, %1, %2, %0;" : "+l"(d) : "l"(a), "l"(b));
}
__device__ __forceinline__ float hsum2(unsigned long long v) {
    float lo, hi;
    asm("mov.b64 {%0, %1}, %2;" : "=f"(lo), "=f"(hi) : "l"(v));
    return lo + hi;
}
__device__ __forceinline__ float sigf(float x) {
    return 1.f / (1.f + __expf(-x));
}

// ---------------------------------------------------------------------------
// Kernel 1: recurrent scan
//   tid = jg*4 + q ; jg in [0,64), q in [0,4). Rows r0=2q, r1=2q+1.
//   Thread owns outputs j = jg + 64*i (i=0..5) for both rows:
//     i=0,1 -> r-gate of units {jg, jg+64}; i=2,3 -> z; i=4,5 -> n.
//   Per step: write hv[t&1] -> BAR -> GEMM(read hv[t&1]) -> STG h to g_h.
//   WAR on hv[t&1] (rewritten at t+2) is fenced by BAR at t+1: race-free
//   with exactly one barrier per step.
// ---------------------------------------------------------------------------
__global__ void __launch_bounds__(256, 1) grud_recurrent(
    const float* __restrict__ x,
    const float* __restrict__ x_mean,
    const float* __restrict__ dxw_g, const float* __restrict__ dxb_g,
    const float* __restrict__ dhw_g, const float* __restrict__ dhb_g,
    const float* __restrict__ w_ih, const float* __restrict__ w_hh,
    const float* __restrict__ b_ih, const float* __restrict__ b_hh)
{
    extern __shared__ float sm[];
    float* Ws  = sm;                   // [384][HP]  combined [w_hh | w_ih]
    float* hv0 = Ws + G3 * HP;         // [8][HP]    buffer 0
    float* hv1 = hv0 + NB * HP;        // [8][HP]    buffer 1

    const int tid = threadIdx.x;
    const int q   = tid & 3;
    const int jg  = tid >> 2;          // 0..63
    const int b0  = blockIdx.x * NB;
    const int r0  = 2 * q, r1 = 2 * q + 1;

    // Fill combined weight tile: cols 0..127 = w_hh, 128..139 = w_ih.
    for (int idx = tid; idx < G3 * H; idx += 256)
        Ws[(idx >> 7) * HP + (idx & 127)] = w_hh[idx];
    for (int idx = tid; idx < G3 * 12; idx += 256)
        Ws[(idx / 12) * HP + H + (idx % 12)] = w_ih[idx];

    // Per-thread constants.
    float bc[4], bhn[2], bin[2];
    #pragma unroll
    for (int i = 0; i < 4; i++) {
        int j = jg + 64 * i;
        bc[i] = b_ih[j] + b_hh[j];
    }
    #pragma unroll
    for (int iu = 0; iu < 2; iu++) {
        int j = 256 + jg + 64 * iu;
        bhn[iu] = b_hh[j]; bin[iu] = b_ih[j];
    }
    float dhw[2], dhb[2];
    #pragma unroll
    for (int iu = 0; iu < 2; iu++) { dhw[iu] = dhw_g[jg + 64 * iu]; dhb[iu] = dhb_g[jg + 64 * iu]; }
    float dxw = 0.f, dxb = 0.f, xm = 0.f;
    if (jg < C) { dxw = dxw_g[jg]; dxb = dxb_g[jg]; xm = x_mean[jg]; }

    float hprev[2][2] = {{0.f, 0.f}, {0.f, 0.f}};   // [iu][rr]
    float running[2] = {0.f, 0.f}, xlast[2] = {0.f, 0.f};

    // Direct-STG bases for the thread's 2 rows (stores at col jg + 64*iu).
    float* gout0 = &g_h[((size_t)(b0 + r0) * T) * H + jg];
    float* gout1 = &g_h[((size_t)(b0 + r1) * T) * H + jg];

    // Prefetch x(t=0) for both rows.
    const size_t xb0 = ((size_t)(b0 + r0) * T) * XD;
    const size_t xb1 = ((size_t)(b0 + r1) * T) * XD;
    float p_dt[2], p_xv[2] = {0.f, 0.f}, p_mv[2] = {0.f, 0.f};
    p_dt[0] = x[xb0 + 12]; p_dt[1] = x[xb1 + 12];
    if (jg < C) {
        p_xv[0] = x[xb0 + jg];     p_xv[1] = x[xb1 + jg];
        p_mv[0] = x[xb0 + C + jg]; p_mv[1] = x[xb1 + C + jg];
    }

    __syncthreads();

    for (int t = 0; t < T; t++) {
        float* hv = (t & 1) ? hv1 : hv0;

        const float dtv[2] = {p_dt[0], p_dt[1]};
        const float xvv[2] = {p_xv[0], p_xv[1]};
        const float mvv[2] = {p_mv[0], p_mv[1]};

        // Prefetch x(t+1): hides LDG latency behind this step's GEMM.
        if (t + 1 < T) {
            size_t o0 = xb0 + (size_t)(t + 1) * XD, o1 = xb1 + (size_t)(t + 1) * XD;
            p_dt[0] = x[o0 + 12]; p_dt[1] = x[o1 + 12];
            if (jg < C) {
                p_xv[0] = x[o0 + jg];     p_xv[1] = x[o1 + jg];
                p_mv[0] = x[o0 + C + jg]; p_mv[1] = x[o1 + C + jg];
            }
        }

        // h_dec = gamma_h * h_prev (4 states in registers).
        float hd[2][2];
        #pragma unroll
        for (int rr = 0; rr < 2; rr++) {
            int row = r0 + rr;
            #pragma unroll
            for (int iu = 0; iu < 2; iu++) {
                float g = __expf(-fmaxf(fmaf(dtv[rr], dhw[iu], dhb[iu]), 0.f));
                float v = g * hprev[iu][rr];
                hd[iu][rr] = v;
                hv[row * HP + jg + 64 * iu] = v;
            }
        }
        // Input scans + x_hat (threads jg<6 own feature c=jg of rows r0,r1).
        if (jg < C) {
            #pragma unroll
            for (int rr = 0; rr < 2; rr++) {
                int row = r0 + rr;
                float xv = xvv[rr], m = mvv[rr];
                bool obs = (m > 0.5f);
                running[rr] = obs ? 0.f : (running[rr] + dtv[rr]);
                float gx = __expf(-fmaxf(fmaf(running[rr], dxw, dxb), 0.f));
                xlast[rr] = obs ? xv : xlast[rr];
                float xh = m * xv + (1.f - m) * (gx * xlast[rr] + (1.f - gx) * xm);
                hv[row * HP + H + jg]     = xh;   // gru_in[0:6]  = x_hat
                hv[row * HP + H + C + jg] = m;    // gru_in[6:12] = m
            }
        }
        __syncthreads();   // the ONLY barrier per step

        // GEMM: 6 outputs x 2 rows; K=140 in 16B chunks.
        // acch[i] (i<4): full r/z sums (gh+gi folded). acch[4..5]: gh_n.
        // acci[iu]: gi_n (kb 32..34) — n = tanh(gi_n + r*gh_n).
        unsigned long long acch[6][2], acci[2][2];
        #pragma unroll
        for (int i = 0; i < 6; i++) { acch[i][0] = 0ull; acch[i][1] = 0ull; }
        acci[0][0] = acci[0][1] = acci[1][0] = acci[1][1] = 0ull;

        const float* h0 = &hv[r0 * HP];
        const float* h1 = &hv[r1 * HP];
        const float* wb = &Ws[jg * HP];
        #pragma unroll
        for (int kb = 0; kb < 32; kb++) {
            ulonglong2 hp0 = *(const ulonglong2*)&h0[4 * kb];
            ulonglong2 hp1 = *(const ulonglong2*)&h1[4 * kb];
            #pragma unroll
            for (int i = 0; i < 6; i++) {
                ulonglong2 wp = *(const ulonglong2*)&wb[i * 64 * HP + 4 * kb];
                fma2(acch[i][0], hp0.x, wp.x); fma2(acch[i][0], hp0.y, wp.y);
                fma2(acch[i][1], hp1.x, wp.x); fma2(acch[i][1], hp1.y, wp.y);
            }
        }
        #pragma unroll
        for (int kb = 32; kb < 35; kb++) {
            ulonglong2 hp0 = *(const ulonglong2*)&h0[4 * kb];
            ulonglong2 hp1 = *(const ulonglong2*)&h1[4 * kb];
            #pragma unroll
            for (int i = 0; i < 4; i++) {           // r,z: fold gi into acch
                ulonglong2 wp = *(const ulonglong2*)&wb[i * 64 * HP + 4 * kb];
                fma2(acch[i][0], hp0.x, wp.x); fma2(acch[i][0], hp0.y, wp.y);
                fma2(acch[i][1], hp1.x, wp.x); fma2(acch[i][1], hp1.y, wp.y);
            }
            #pragma unroll
            for (int iu = 0; iu < 2; iu++) {        // n: gi kept separate
                ulonglong2 wp = *(const ulonglong2*)&wb[(4 + iu) * 64 * HP + 4 * kb];
                fma2(acci[iu][0], hp0.x, wp.x); fma2(acci[iu][0], hp0.y, wp.y);
                fma2(acci[iu][1], hp1.x, wp.x); fma2(acci[iu][1], hp1.y, wp.y);
            }
        }

        // Gates + state update; store h directly to g_h (4 STG.32).
        float* gt0 = gout0 + (size_t)t * H;
        float* gt1 = gout1 + (size_t)t * H;
        #pragma unroll
        for (int rr = 0; rr < 2; rr++) {
            float* gt = rr ? gt1 : gt0;
            #pragma unroll
            for (int iu = 0; iu < 2; iu++) {
                float rg  = sigf(hsum2(acch[iu][rr])     + bc[iu]);
                float z   = sigf(hsum2(acch[2 + iu][rr]) + bc[2 + iu]);
                float ghn = hsum2(acch[4 + iu][rr]) + bhn[iu];
                float gin = hsum2(acci[iu][rr])     + bin[iu];
                float n   = tanhf(fmaf(rg, ghn, gin));
                float hn  = fmaf(z, hd[iu][rr] - n, n);   // (1-z)*n + z*h_dec
                hprev[iu][rr] = hn;
                gt[64 * iu] = hn;
            }
        }
    }
}

// ---------------------------------------------------------------------------
// Kernel 2: output heads over 1M rows; 16-row tiles, 6x2 thread tiles.
//   Stage 1: tid = jg*8 + rp ; jg in [0,32), rp in [0,8). Rows {rp, rp+8}.
//     Outputs j = jg + 32*i: i<4 -> w1 rows (128); i=4,5 -> wu1 rows (64).
//   Stage 2: cg = tid&15 (channel), rr2 = tid>>4 (row 0..15) — conflict-free
//     16-way-broadcast row reads, coalesced channel-contiguous stores.
// ---------------------------------------------------------------------------
__global__ void __launch_bounds__(256, 1) grud_heads(
    const float* __restrict__ w1,  const float* __restrict__ b1,
    const float* __restrict__ w2,  const float* __restrict__ b2,
    const float* __restrict__ wu1, const float* __restrict__ bu1,
    const float* __restrict__ wu2, const float* __restrict__ bu2,
    float* __restrict__ out_pred, float* __restrict__ out_unc)
{
    extern __shared__ float sm[];
    float* w1s  = sm;                     // [128][WP2]
    float* wu1s = w1s  + H * WP2;         // [64][WP2]
    float* w2s  = wu1s + 64 * WP2;        // [6][WP2]
    float* wu2s = w2s  + C * WP2;         // [6][68]
    float* hts  = wu2s + C * 68;          // [16][WP2]
    float* o1s  = hts  + 16 * WP2;        // [16][WP2]
    float* u1s  = o1s  + 16 * WP2;        // [16][68]

    const int tid = threadIdx.x;
    const int rp  = tid & 7;              // row pair index
    const int jg  = tid >> 3;             // 0..31
    const int cg  = tid & 15;             // stage-2 channel group
    const int rr2 = tid >> 4;             // stage-2 row 0..15

    for (int idx = tid; idx < H * H;  idx += 256) w1s [(idx >> 7) * WP2 + (idx & 127)] = w1[idx];
    for (int idx = tid; idx < 64 * H; idx += 256) wu1s[(idx >> 7) * WP2 + (idx & 127)] = wu1[idx];
    for (int idx = tid; idx < C * H;  idx += 256) w2s [(idx >> 7) * WP2 + (idx & 127)] = w2[idx];
    for (int idx = tid; idx < C * 64; idx += 256) wu2s[(idx >> 6) * 68  + (idx & 63)]  = wu2[idx];

    float bias1[6];
    #pragma unroll
    for (int i = 0; i < 4; i++) bias1[i] = b1[jg + 32 * i];
    bias1[4] = bu1[jg]; bias1[5] = bu1[jg + 32];
    float bias2 = 0.f;
    if (cg < C) bias2 = b2[cg];
    else if (cg >= 8 && cg < 8 + C) bias2 = bu2[cg - 8];
    __syncthreads();

    const int tiles_per_cta = (B * T / 16) / gridDim.x;
    const int tbase = blockIdx.x * tiles_per_cta;

    // h-tile register prefetch: 512 float4 needed; 2 per thread.
    const int v0 = tid * 2, v1 = tid * 2 + 1;
    const int rw0 = v0 >> 5, k40 = (v0 & 31) * 4;
    const int rw1 = v1 >> 5, k41 = (v1 & 31) * 4;
    float4 pre0 = *(const float4*)&g_h[((size_t)tbase * 16 + rw0) * H + k40];
    float4 pre1 = *(const float4*)&g_h[((size_t)tbase * 16 + rw1) * H + k41];

    for (int g = 0; g < tiles_per_cta; g++) {
        const size_t row0 = (size_t)(tbase + g) * 16;
        *(float4*)&hts[rw0 * WP2 + k40] = pre0;
        *(float4*)&hts[rw1 * WP2 + k41] = pre1;
        __syncthreads();

        // Issue next tile's gmem loads now; consumed next iteration.
        if (g + 1 < tiles_per_cta) {
            pre0 = *(const float4*)&g_h[(row0 + 16 + rw0) * H + k40];
            pre1 = *(const float4*)&g_h[(row0 + 16 + rw1) * H + k41];
        }

        unsigned long long a[6][2];
        #pragma unroll
        for (int i = 0; i < 6; i++) { a[i][0] = 0ull; a[i][1] = 0ull; }
        const float* h0 = &hts[rp * WP2];
        const float* h1 = &hts[(rp + 8) * WP2];
        #pragma unroll
        for (int kb = 0; kb < 32; kb++) {
            ulonglong2 hp0 = *(const ulonglong2*)&h0[4 * kb];
            ulonglong2 hp1 = *(const ulonglong2*)&h1[4 * kb];
            #pragma unroll
            for (int i = 0; i < 4; i++) {
                ulonglong2 wp = *(const ulonglong2*)&w1s[(jg + 32 * i) * WP2 + 4 * kb];
                fma2(a[i][0], hp0.x, wp.x); fma2(a[i][0], hp0.y, wp.y);
                fma2(a[i][1], hp1.x, wp.x); fma2(a[i][1], hp1.y, wp.y);
            }
            #pragma unroll
            for (int i = 4; i < 6; i++) {
                ulonglong2 wp = *(const ulonglong2*)&wu1s[(jg + 32 * (i - 4)) * WP2 + 4 * kb];
                fma2(a[i][0], hp0.x, wp.x); fma2(a[i][0], hp0.y, wp.y);
                fma2(a[i][1], hp1.x, wp.x); fma2(a[i][1], hp1.y, wp.y);
            }
        }
        #pragma unroll
        for (int rr = 0; rr < 2; rr++) {
            int row = rp + 8 * rr;
            #pragma unroll
            for (int i = 0; i < 4; i++)
                o1s[row * WP2 + jg + 32 * i] = fmaxf(hsum2(a[i][rr]) + bias1[i], 0.f);
            u1s[row * 68 + jg]      = fmaxf(hsum2(a[4][rr]) + bias1[4], 0.f);
            u1s[row * 68 + jg + 32] = fmaxf(hsum2(a[5][rr]) + bias1[5], 0.f);
        }
        __syncthreads();

        // Stage 2: project to C=6 pred / unc channels.
        if (cg < C) {
            unsigned long long acc = 0ull;
            const float* o = &o1s[rr2 * WP2];
            const float* w = &w2s[cg * WP2];
            #pragma unroll
            for (int kb = 0; kb < 32; kb++) {
                ulonglong2 op = *(const ulonglong2*)&o[4 * kb];
                ulonglong2 wp = *(const ulonglong2*)&w[4 * kb];
                fma2(acc, op.x, wp.x); fma2(acc, op.y, wp.y);
            }
            out_pred[(row0 + rr2) * C + cg] = hsum2(acc) + bias2;
        } else if (cg >= 8 && cg < 8 + C) {
            unsigned long long acc = 0ull;
            const float* u = &u1s[rr2 * 68];
            const float* w = &wu2s[(cg - 8) * 68];
            #pragma unroll
            for (int kb = 0; kb < 16; kb++) {
                ulonglong2 up = *(const ulonglong2*)&u[4 * kb];
                ulonglong2 wp = *(const ulonglong2*)&w[4 * kb];
                fma2(acc, up.x, wp.x); fma2(acc, up.y, wp.y);
            }
            float s = hsum2(acc) + bias2;
            out_unc[(row0 + rr2) * C + (cg - 8)] = (s > 20.f) ? s : log1pf(__expf(s));
        }
        __syncthreads();
    }
}

// ---------------------------------------------------------------------------
// Launch
// ---------------------------------------------------------------------------
extern "C" void kernel_launch(void* const* d_in, const int* in_sizes, int n_in,
                              void* d_out, int out_size) {
    const float* x      = (const float*)d_in[0];
    const float* x_mean = (const float*)d_in[1];
    const float* dxw    = (const float*)d_in[2];
    const float* dxb    = (const float*)d_in[3];
    const float* dhw    = (const float*)d_in[4];
    const float* dhb    = (const float*)d_in[5];
    const float* w_ih   = (const float*)d_in[6];
    const float* w_hh   = (const float*)d_in[7];
    const float* b_ih   = (const float*)d_in[8];
    const float* b_hh   = (const float*)d_in[9];
    const float* w1     = (const float*)d_in[10];
    const float* b1     = (const float*)d_in[11];
    const float* w2     = (const float*)d_in[12];
    const float* b2     = (const float*)d_in[13];
    const float* wu1    = (const float*)d_in[14];
    const float* bu1    = (const float*)d_in[15];
    const float* wu2    = (const float*)d_in[16];
    const float* bu2    = (const float*)d_in[17];

    float* pred = (float*)d_out;
    float* unc  = pred + (size_t)B * T * C;

    const int sm1 = (G3 * HP + 2 * NB * HP) * 4;                             // 224,000 B
    const int sm2 = (H * WP2 + 64 * WP2 + C * WP2 + C * 68 +
                     16 * WP2 + 16 * WP2 + 16 * 68) * 4;                     // 127,424 B

    cudaFuncSetAttribute(grud_recurrent, cudaFuncAttributeMaxDynamicSharedMemorySize, sm1);
    cudaFuncSetAttribute(grud_heads,     cudaFuncAttributeMaxDynamicSharedMemorySize, sm2);

    grud_recurrent<<<B / NB, 256, sm1>>>(x, x_mean, dxw, dxb, dhw, dhb,
                                         w_ih, w_hh, b_ih, b_hh);
    grud_heads<<<1024, 256, sm2>>>(w1, b1, w2, b2, wu1, bu1, wu2, bu2, pred, unc);
}